// round 12
// baseline (speedup 1.0000x reference)
#include <cuda_runtime.h>
#include <cuda_fp16.h>
#include <math.h>

#define NN 50000
#define EE 1600000
#define ETOT (EE + NN)
#define G64BLK ((NN + 127) / 128)
#define EBLK ((ETOT + 255) / 256)

// ---------------- scratch ----------------
__device__ uint4  g_h16v[NN * 8];    // fp16 h, 16B-aligned (64 halves per node)
__device__ float  g_x2[NN * 64];
__device__ float  g_als[NN * 4];
__device__ float  g_ald[NN * 4];
__device__ int    g_deg[NN];
__device__ int    g_off[NN + 1];
__device__ int    g_cur[NN];
__device__ int    g_csr[ETOT];

// ================= CSR build =================
__global__ void hist_kernel(const int* __restrict__ ei) {
    int e = blockIdx.x * blockDim.x + threadIdx.x;
    if (e >= ETOT) return;
    int d = (e < EE) ? ei[EE + e] : (e - EE);
    atomicAdd(&g_deg[d], 1);
}

__global__ void scan_kernel() {
    __shared__ int partial[1024];
    int t = threadIdx.x;
    const int C = (NN + 1023) / 1024;
    int b0 = t * C;
    int b1 = min(b0 + C, NN);
    int sum = 0;
    for (int i = b0; i < b1; i++) sum += g_deg[i];
    partial[t] = sum;
    __syncthreads();
    for (int off = 1; off < 1024; off <<= 1) {
        int v = (t >= off) ? partial[t - off] : 0;
        __syncthreads();
        partial[t] += v;
        __syncthreads();
    }
    int run = (t == 0) ? 0 : partial[t - 1];
    for (int i = b0; i < b1; i++) {
        g_off[i] = run;
        g_cur[i] = run;
        run += g_deg[i];
    }
    if (t == 1023) g_off[NN] = run;
}

// ===== fused: layer-1 GEMM (blocks [0, G64BLK)) || CSR scatter (rest) =====
__global__ void __launch_bounds__(256)
fused_gemm1_scatter(const float* __restrict__ X, const float* __restrict__ W,
                    const float* __restrict__ a_s, const float* __restrict__ a_d,
                    const int* __restrict__ ei) {
    constexpr int IN = 128;
    constexpr int KT = 32;
    constexpr int SXS = 132;
    __shared__ float sW[KT][64];
    __shared__ float sX2[KT][SXS];
    int t = threadIdx.x;

    if (blockIdx.x >= G64BLK) {
        int e = (blockIdx.x - G64BLK) * 256 + t;
        if (e < ETOT) {
            int s, d;
            if (e < EE) { s = ei[e]; d = ei[EE + e]; } else { s = e - EE; d = s; }
            int pos = atomicAdd(&g_cur[d], 1);
            g_csr[pos] = s;
        }
        return;
    }

    int tx = t & 15, ty = t >> 4;
    int row0 = blockIdx.x * 128;
    float acc[8][4];
#pragma unroll
    for (int r = 0; r < 8; r++)
#pragma unroll
        for (int c = 0; c < 4; c++) acc[r][c] = 0.f;

    for (int kt = 0; kt < IN; kt += KT) {
#pragma unroll
        for (int i = t; i < KT * 16; i += 256) {
            int kk = i >> 4;
            int c4 = (i & 15) << 2;
            *(float4*)&sW[kk][c4] = *(const float4*)&W[(kt + kk) * 64 + c4];
        }
#pragma unroll
        for (int i = t; i < 128 * (KT / 4); i += 256) {
            int r = i >> 3;
            int k4 = (i & 7) << 2;
            int gr = row0 + r;
            float4 v = (gr < NN) ? *(const float4*)&X[gr * IN + kt + k4]
                                 : make_float4(0.f, 0.f, 0.f, 0.f);
            sX2[k4 + 0][r] = v.x;
            sX2[k4 + 1][r] = v.y;
            sX2[k4 + 2][r] = v.z;
            sX2[k4 + 3][r] = v.w;
        }
        __syncthreads();
#pragma unroll
        for (int k = 0; k < KT; k++) {
            float4 w4 = *(float4*)&sW[k][tx * 4];
            float4 xa = *(float4*)&sX2[k][ty * 8];
            float4 xb = *(float4*)&sX2[k][ty * 8 + 4];
            float xr[8] = {xa.x, xa.y, xa.z, xa.w, xb.x, xb.y, xb.z, xb.w};
#pragma unroll
            for (int r = 0; r < 8; r++) {
                acc[r][0] += xr[r] * w4.x;
                acc[r][1] += xr[r] * w4.y;
                acc[r][2] += xr[r] * w4.z;
                acc[r][3] += xr[r] * w4.w;
            }
        }
        __syncthreads();
    }

    int h = tx >> 2;
    float4 asv = *(const float4*)&a_s[h * 16 + (tx & 3) * 4];
    float4 adv = *(const float4*)&a_d[h * 16 + (tx & 3) * 4];
    __half2* h2out = (__half2*)g_h16v;
#pragma unroll
    for (int r = 0; r < 8; r++) {
        int gr = row0 + ty * 8 + r;
        float ps = acc[r][0] * asv.x + acc[r][1] * asv.y + acc[r][2] * asv.z + acc[r][3] * asv.w;
        float pd = acc[r][0] * adv.x + acc[r][1] * adv.y + acc[r][2] * adv.z + acc[r][3] * adv.w;
        ps += __shfl_xor_sync(0xffffffffu, ps, 1);
        ps += __shfl_xor_sync(0xffffffffu, ps, 2);
        pd += __shfl_xor_sync(0xffffffffu, pd, 1);
        pd += __shfl_xor_sync(0xffffffffu, pd, 2);
        if (gr < NN) {
            h2out[(gr * 64 + tx * 4) >> 1] = __floats2half2_rn(acc[r][0], acc[r][1]);
            h2out[((gr * 64 + tx * 4) >> 1) + 1] = __floats2half2_rn(acc[r][2], acc[r][3]);
            if ((tx & 3) == 0) {
                g_als[gr * 4 + h] = ps;
                g_ald[gr * 4 + h] = pd;
            }
        }
    }
}

// ------- GEMM 64-wide (layer 2), 128-row tile, fused al + fp16 out ----
template <int IN>
__global__ void __launch_bounds__(256)
gemm64(const float* __restrict__ X, const float* __restrict__ W,
       const float* __restrict__ a_s, const float* __restrict__ a_d) {
    constexpr int KT = 32;
    constexpr int SXS = 132;
    __shared__ float sW[KT][64];
    __shared__ float sX2[KT][SXS];
    int t = threadIdx.x;
    int tx = t & 15, ty = t >> 4;
    int row0 = blockIdx.x * 128;
    float acc[8][4];
#pragma unroll
    for (int r = 0; r < 8; r++)
#pragma unroll
        for (int c = 0; c < 4; c++) acc[r][c] = 0.f;

    for (int kt = 0; kt < IN; kt += KT) {
#pragma unroll
        for (int i = t; i < KT * 16; i += 256) {
            int kk = i >> 4;
            int c4 = (i & 15) << 2;
            *(float4*)&sW[kk][c4] = *(const float4*)&W[(kt + kk) * 64 + c4];
        }
#pragma unroll
        for (int i = t; i < 128 * (KT / 4); i += 256) {
            int r = i >> 3;
            int k4 = (i & 7) << 2;
            int gr = row0 + r;
            float4 v = (gr < NN) ? *(const float4*)&X[gr * IN + kt + k4]
                                 : make_float4(0.f, 0.f, 0.f, 0.f);
            sX2[k4 + 0][r] = v.x;
            sX2[k4 + 1][r] = v.y;
            sX2[k4 + 2][r] = v.z;
            sX2[k4 + 3][r] = v.w;
        }
        __syncthreads();
#pragma unroll
        for (int k = 0; k < KT; k++) {
            float4 w4 = *(float4*)&sW[k][tx * 4];
            float4 xa = *(float4*)&sX2[k][ty * 8];
            float4 xb = *(float4*)&sX2[k][ty * 8 + 4];
            float xr[8] = {xa.x, xa.y, xa.z, xa.w, xb.x, xb.y, xb.z, xb.w};
#pragma unroll
            for (int r = 0; r < 8; r++) {
                acc[r][0] += xr[r] * w4.x;
                acc[r][1] += xr[r] * w4.y;
                acc[r][2] += xr[r] * w4.z;
                acc[r][3] += xr[r] * w4.w;
            }
        }
        __syncthreads();
    }

    int h = tx >> 2;
    float4 asv = *(const float4*)&a_s[h * 16 + (tx & 3) * 4];
    float4 adv = *(const float4*)&a_d[h * 16 + (tx & 3) * 4];
    __half2* h2out = (__half2*)g_h16v;
#pragma unroll
    for (int r = 0; r < 8; r++) {
        int gr = row0 + ty * 8 + r;
        float ps = acc[r][0] * asv.x + acc[r][1] * asv.y + acc[r][2] * asv.z + acc[r][3] * asv.w;
        float pd = acc[r][0] * adv.x + acc[r][1] * adv.y + acc[r][2] * adv.z + acc[r][3] * adv.w;
        ps += __shfl_xor_sync(0xffffffffu, ps, 1);
        ps += __shfl_xor_sync(0xffffffffu, ps, 2);
        pd += __shfl_xor_sync(0xffffffffu, pd, 1);
        pd += __shfl_xor_sync(0xffffffffu, pd, 2);
        if (gr < NN) {
            h2out[(gr * 64 + tx * 4) >> 1] = __floats2half2_rn(acc[r][0], acc[r][1]);
            h2out[((gr * 64 + tx * 4) >> 1) + 1] = __floats2half2_rn(acc[r][2], acc[r][3]);
            if ((tx & 3) == 0) {
                g_als[gr * 4 + h] = ps;
                g_ald[gr * 4 + h] = pd;
            }
        }
    }
}

// ------- GEMM layer 3 (64->16): fused al epilogue, fp16-only output -------
__global__ void gemm16(const float* __restrict__ X, const float* __restrict__ W,
                       const float* __restrict__ a_s, const float* __restrict__ a_d) {
    constexpr int IN = 64, OUT = 16;
    constexpr int RB = 64;
    __shared__ float sW[IN * OUT];
    __shared__ float sX[RB * IN];
    int t = threadIdx.x;
    int tx = t & 15, ty = t >> 4;
    int row0 = blockIdx.x * RB;

    for (int i = t; i < IN * OUT; i += 256) sW[i] = W[i];
    for (int i = t; i < RB * IN; i += 256) {
        int r = row0 + i / IN;
        sX[i] = (r < NN) ? X[r * IN + (i % IN)] : 0.f;
    }
    __syncthreads();

    float acc[4];
#pragma unroll
    for (int rr = 0; rr < 4; rr++) acc[rr] = 0.f;
    const float* xs = &sX[ty * 4 * IN];
    for (int k = 0; k < IN; k++) {
        float wv = sW[k * OUT + tx];
#pragma unroll
        for (int rr = 0; rr < 4; rr++) acc[rr] += xs[rr * IN + k] * wv;
    }
    float asx = __ldg(&a_s[tx]), adx = __ldg(&a_d[tx]);
    __half* h16 = (__half*)g_h16v;
#pragma unroll
    for (int rr = 0; rr < 4; rr++) {
        int r = row0 + ty * 4 + rr;
        float ps = acc[rr] * asx;
        float pd = acc[rr] * adx;
#pragma unroll
        for (int off = 1; off < 16; off <<= 1) {
            ps += __shfl_xor_sync(0xffffffffu, ps, off);
            pd += __shfl_xor_sync(0xffffffffu, pd, off);
        }
        if (r < NN) {
            h16[r * OUT + tx] = __float2half_rn(acc[rr]);
            if (tx == 0) {
                g_als[r] = ps;
                g_ald[r] = pd;
            }
        }
    }
}

__device__ __forceinline__ float lrelu_exp(float v) {
    v = (v > 0.f) ? v : 0.2f * v;
    return __expf(v);
}

// ============ fused gather-aggregation, 64-wide (layers 1 & 2) ============
// warp per dst node; 2 edge-halves of 16 lanes; lane owns 4 cols via LDG.64.
__global__ void __launch_bounds__(256)
agg64(const float* __restrict__ b,
      const float* __restrict__ gg, const float* __restrict__ bb,
      const float* __restrict__ mm, const float* __restrict__ vv,
      float* __restrict__ xnext) {
    __shared__ float2 sh_sex[8][4][34];
    int w = threadIdx.x >> 5;
    int lane = threadIdx.x & 31;
    int n = (blockIdx.x * blockDim.x + threadIdx.x) >> 5;
    if (n >= NN) return;
    int eg = lane >> 4;        // edge half 0/1
    int cq = lane & 15;        // col quad: cols 4*cq .. 4*cq+3
    int h = cq >> 2;           // head of those cols
    float4 ad4 = *(const float4*)&g_ald[n * 4];
    float acc0 = 0.f, acc1 = 0.f, acc2 = 0.f, acc3 = 0.f, den = 0.f;
    const uint2* pu2 = (const uint2*)g_h16v;
    int beg = g_off[n], end = g_off[n + 1];
    for (int base = beg; base < end; base += 32) {
        int idx = base + lane;
        bool valid = idx < end;
        int s = valid ? g_csr[idx] : 0;
        float4 as4 = *(const float4*)&g_als[s * 4];
        float sf = __int_as_float(s * 16);     // row base in uint2 units
        float e0 = valid ? lrelu_exp(as4.x + ad4.x) : 0.f;
        float e1 = valid ? lrelu_exp(as4.y + ad4.y) : 0.f;
        float e2 = valid ? lrelu_exp(as4.z + ad4.z) : 0.f;
        float e3 = valid ? lrelu_exp(as4.w + ad4.w) : 0.f;
        __syncwarp();
        sh_sex[w][0][lane] = make_float2(sf, e0);
        sh_sex[w][1][lane] = make_float2(sf, e1);
        sh_sex[w][2][lane] = make_float2(sf, e2);
        sh_sex[w][3][lane] = make_float2(sf, e3);
        __syncwarp();
        int nk8 = (min(32, end - base) + 7) & ~7;
        for (int j0 = 0; j0 < nk8; j0 += 8) {
#pragma unroll
            for (int u = 0; u < 4; u++) {
                int j = j0 + 2 * u + eg;
                float2 p = sh_sex[w][h][j];
                int sj16 = __float_as_int(p.x);
                float ex = p.y;
                uint2 v = __ldg(&pu2[sj16 + cq]);
                float2 f0 = __half22float2(*(__half2*)&v.x);
                float2 f1 = __half22float2(*(__half2*)&v.y);
                acc0 += ex * f0.x;
                acc1 += ex * f0.y;
                acc2 += ex * f1.x;
                acc3 += ex * f1.y;
                den += ex;
            }
        }
    }
    acc0 += __shfl_xor_sync(0xffffffffu, acc0, 16);
    acc1 += __shfl_xor_sync(0xffffffffu, acc1, 16);
    acc2 += __shfl_xor_sync(0xffffffffu, acc2, 16);
    acc3 += __shfl_xor_sync(0xffffffffu, acc3, 16);
    den += __shfl_xor_sync(0xffffffffu, den, 16);
    if (lane < 16) {
        float inv = 1.f / (den + 1e-16f);
        int c0 = 4 * cq;
        float a[4] = {acc0 * inv, acc1 * inv, acc2 * inv, acc3 * inv};
        float o[4];
#pragma unroll
        for (int i = 0; i < 4; i++) {
            int col = c0 + i;
            float y = (a[i] + __ldg(&b[col]) - __ldg(&mm[col])) *
                          rsqrtf(__ldg(&vv[col]) + 1e-5f) * __ldg(&gg[col]) +
                      __ldg(&bb[col]);
            o[i] = fmaxf(y, 0.f);
        }
        *(float4*)&xnext[n * 64 + c0] = make_float4(o[0], o[1], o[2], o[3]);
    }
}

// ==== fused gather-aggregation 16-wide + BN + fc1 + fc2 (layer 3 + head) ====
// warp per dst node; 8 edge-groups of 4 lanes; lane owns 4 cols via uint2.
// After the cross-group reduce, lanes 0-3 hold the 16 cols; they compute BN,
// partial fc1, xor-combine within the 4-lane group, lane 0 finishes fc2.
__global__ void __launch_bounds__(256)
agg16ep3(const float* __restrict__ b3, const float* __restrict__ gg,
         const float* __restrict__ bb, const float* __restrict__ mm,
         const float* __restrict__ vv, const float* __restrict__ fw1,
         const float* __restrict__ fb1, const float* __restrict__ fw2,
         const float* __restrict__ fb2, float* __restrict__ out) {
    __shared__ float2 sh_sex[8][33];
    int w = threadIdx.x >> 5;
    int lane = threadIdx.x & 31;
    int n = (blockIdx.x * blockDim.x + threadIdx.x) >> 5;
    if (n >= NN) return;
    int q = lane >> 2;        // edge-group 0..7
    int cg = lane & 3;        // uint2 col group: cols 4*cg .. 4*cg+3
    float ad = g_ald[n];
    float a0 = 0.f, a1 = 0.f, a2 = 0.f, a3 = 0.f, den = 0.f;
    const uint2* pu2 = (const uint2*)g_h16v;   // row = 16 halves = 4 uint2
    int beg = g_off[n], end = g_off[n + 1];
    for (int base = beg; base < end; base += 32) {
        int idx = base + lane;
        bool valid = idx < end;
        int s = valid ? g_csr[idx] : 0;
        float ex = valid ? lrelu_exp(__ldg(&g_als[s]) + ad) : 0.f;
        __syncwarp();
        sh_sex[w][lane] = make_float2(__int_as_float(s * 4), ex);
        __syncwarp();
        int nk8 = (min(32, end - base) + 7) & ~7;
        for (int j0 = 0; j0 < nk8; j0 += 8) {
            int j = j0 + q;
            float2 p = sh_sex[w][j];
            int sj4 = __float_as_int(p.x);
            float exj = p.y;
            uint2 v = __ldg(&pu2[sj4 + cg]);
            float2 f0 = __half22float2(*(__half2*)&v.x);
            float2 f1 = __half22float2(*(__half2*)&v.y);
            a0 += exj * f0.x;
            a1 += exj * f0.y;
            a2 += exj * f1.x;
            a3 += exj * f1.y;
            den += exj;
        }
    }
    // reduce across the 8 edge groups (lanes with same cg)
#pragma unroll
    for (int off = 4; off <= 16; off <<= 1) {
        a0 += __shfl_xor_sync(0xffffffffu, a0, off);
        a1 += __shfl_xor_sync(0xffffffffu, a1, off);
        a2 += __shfl_xor_sync(0xffffffffu, a2, off);
        a3 += __shfl_xor_sync(0xffffffffu, a3, off);
        den += __shfl_xor_sync(0xffffffffu, den, off);
    }
    // lanes 0-3 hold cols 4*cg..4*cg+3; all lanes run (converged shfls).
    float inv = 1.f / (den + 1e-16f);
    int c0 = 4 * cg;
    float tt[4];
#pragma unroll
    for (int i = 0; i < 4; i++) {
        int col = c0 + i;
        float y = (fmaf(a0, 0.f, (i == 0 ? a0 : i == 1 ? a1 : i == 2 ? a2 : a3)) * inv +
                   __ldg(&b3[col]) - __ldg(&mm[col])) *
                      rsqrtf(__ldg(&vv[col]) + 1e-5f) * __ldg(&gg[col]) +
                  __ldg(&bb[col]);
        tt[i] = fmaxf(y, 0.f);
    }
    // partial fc1 over this lane's 4 cols, all 8 outputs
    float z[8];
#pragma unroll
    for (int oo = 0; oo < 8; oo++) {
        float zz = 0.f;
#pragma unroll
        for (int i = 0; i < 4; i++) zz += tt[i] * __ldg(&fw1[(c0 + i) * 8 + oo]);
        z[oo] = zz;
    }
#pragma unroll
    for (int off = 1; off <= 2; off <<= 1)
#pragma unroll
        for (int oo = 0; oo < 8; oo++) z[oo] += __shfl_xor_sync(0xffffffffu, z[oo], off);
    if (lane == 0) {
        float o = __ldg(&fb2[0]);
#pragma unroll
        for (int oo = 0; oo < 8; oo++) {
            float zz = fmaxf(z[oo] + __ldg(&fb1[oo]), 0.f);
            o += zz * __ldg(&fw2[oo]);
        }
        out[n] = o;
    }
}

// ---------------- launch ----------------
extern "C" void kernel_launch(void* const* d_in, const int* in_sizes, int n_in,
                              void* d_out, int out_size) {
    const float* x = (const float*)d_in[0];
    const int* ei = (const int*)d_in[1];
    const float* W1 = (const float*)d_in[2];
    const float* as1 = (const float*)d_in[3];
    const float* ad1 = (const float*)d_in[4];
    const float* b1 = (const float*)d_in[5];
    const float* g1 = (const float*)d_in[6];
    const float* bb1 = (const float*)d_in[7];
    const float* m1 = (const float*)d_in[8];
    const float* v1 = (const float*)d_in[9];
    const float* W2 = (const float*)d_in[10];
    const float* as2 = (const float*)d_in[11];
    const float* ad2 = (const float*)d_in[12];
    const float* b2 = (const float*)d_in[13];
    const float* g2 = (const float*)d_in[14];
    const float* bb2 = (const float*)d_in[15];
    const float* m2 = (const float*)d_in[16];
    const float* v2 = (const float*)d_in[17];
    const float* W3 = (const float*)d_in[18];
    const float* as3 = (const float*)d_in[19];
    const float* ad3 = (const float*)d_in[20];
    const float* b3 = (const float*)d_in[21];
    const float* g3 = (const float*)d_in[22];
    const float* bb3 = (const float*)d_in[23];
    const float* m3 = (const float*)d_in[24];
    const float* v3 = (const float*)d_in[25];
    const float* fw1 = (const float*)d_in[26];
    const float* fb1 = (const float*)d_in[27];
    const float* fw2 = (const float*)d_in[28];
    const float* fb2 = (const float*)d_in[29];
    float* out = (float*)d_out;

    float* px2 = nullptr;
    int* pdeg = nullptr;
    cudaGetSymbolAddress((void**)&px2, g_x2);
    cudaGetSymbolAddress((void**)&pdeg, g_deg);

    const int TB = 256;
    int aggblk = (NN * 32 + TB - 1) / TB;

    // ---- CSR: hist + scan, then scatter fused with layer-1 GEMM ----
    cudaMemsetAsync(pdeg, 0, NN * sizeof(int));
    hist_kernel<<<EBLK, TB>>>(ei);
    scan_kernel<<<1, 1024>>>();

    // ---- Layer 1 GEMM || CSR scatter ----
    fused_gemm1_scatter<<<G64BLK + EBLK, TB>>>(x, W1, as1, ad1, ei);
    agg64<<<aggblk, TB>>>(b1, g1, bb1, m1, v1, px2);

    // ---- Layer 2 ----
    gemm64<64><<<G64BLK, TB>>>(px2, W2, as2, ad2);
    agg64<<<aggblk, TB>>>(b2, g2, bb2, m2, v2, px2);

    // ---- Layer 3 (GEMM + al) then fused agg+BN+MLP head ----
    gemm16<<<(NN + 63) / 64, TB>>>(px2, W3, as3, ad3);
    agg16ep3<<<aggblk, TB>>>(b3, g3, bb3, m3, v3, fw1, fb1, fw2, fb2, out);
}

// round 13
// speedup vs baseline: 1.0785x; 1.0785x over previous
#include <cuda_runtime.h>
#include <cuda_fp16.h>
#include <math.h>

#define NN 50000
#define EE 1600000
#define ETOT (EE + NN)
#define G64BLK ((NN + 127) / 128)
#define EBLK ((ETOT + 255) / 256)

// ---------------- scratch ----------------
__device__ uint4  g_h16v[NN * 8];    // fp16 h, 16B-aligned (64 halves per node)
__device__ float  g_x2[NN * 64];
__device__ float  g_als[NN * 4];
__device__ float  g_ald[NN * 4];
__device__ float  g_acc[NN * 16];
__device__ int    g_deg[NN];
__device__ int    g_off[NN + 1];
__device__ int    g_cur[NN];
__device__ int    g_csr[ETOT];

// ================= CSR build =================
__global__ void hist_kernel(const int* __restrict__ ei) {
    int e = blockIdx.x * blockDim.x + threadIdx.x;
    if (e >= ETOT) return;
    int d = (e < EE) ? ei[EE + e] : (e - EE);
    atomicAdd(&g_deg[d], 1);
}

__global__ void scan_kernel() {
    __shared__ int partial[1024];
    int t = threadIdx.x;
    const int C = (NN + 1023) / 1024;
    int b0 = t * C;
    int b1 = min(b0 + C, NN);
    int sum = 0;
    for (int i = b0; i < b1; i++) sum += g_deg[i];
    partial[t] = sum;
    __syncthreads();
    for (int off = 1; off < 1024; off <<= 1) {
        int v = (t >= off) ? partial[t - off] : 0;
        __syncthreads();
        partial[t] += v;
        __syncthreads();
    }
    int run = (t == 0) ? 0 : partial[t - 1];
    for (int i = b0; i < b1; i++) {
        g_off[i] = run;
        g_cur[i] = run;
        run += g_deg[i];
    }
    if (t == 1023) g_off[NN] = run;
}

// ===== fused: layer-1 GEMM (blocks [0, G64BLK)) || CSR scatter (rest) =====
__global__ void __launch_bounds__(256)
fused_gemm1_scatter(const float* __restrict__ X, const float* __restrict__ W,
                    const float* __restrict__ a_s, const float* __restrict__ a_d,
                    const int* __restrict__ ei) {
    constexpr int IN = 128;
    constexpr int KT = 32;
    constexpr int SXS = 132;
    __shared__ float sW[KT][64];
    __shared__ float sX2[KT][SXS];
    int t = threadIdx.x;

    if (blockIdx.x >= G64BLK) {
        int e = (blockIdx.x - G64BLK) * 256 + t;
        if (e < ETOT) {
            int s, d;
            if (e < EE) { s = ei[e]; d = ei[EE + e]; } else { s = e - EE; d = s; }
            int pos = atomicAdd(&g_cur[d], 1);
            g_csr[pos] = s;
        }
        return;
    }

    int tx = t & 15, ty = t >> 4;
    int row0 = blockIdx.x * 128;
    float acc[8][4];
#pragma unroll
    for (int r = 0; r < 8; r++)
#pragma unroll
        for (int c = 0; c < 4; c++) acc[r][c] = 0.f;

    for (int kt = 0; kt < IN; kt += KT) {
#pragma unroll
        for (int i = t; i < KT * 16; i += 256) {
            int kk = i >> 4;
            int c4 = (i & 15) << 2;
            *(float4*)&sW[kk][c4] = *(const float4*)&W[(kt + kk) * 64 + c4];
        }
#pragma unroll
        for (int i = t; i < 128 * (KT / 4); i += 256) {
            int r = i >> 3;
            int k4 = (i & 7) << 2;
            int gr = row0 + r;
            float4 v = (gr < NN) ? *(const float4*)&X[gr * IN + kt + k4]
                                 : make_float4(0.f, 0.f, 0.f, 0.f);
            sX2[k4 + 0][r] = v.x;
            sX2[k4 + 1][r] = v.y;
            sX2[k4 + 2][r] = v.z;
            sX2[k4 + 3][r] = v.w;
        }
        __syncthreads();
#pragma unroll
        for (int k = 0; k < KT; k++) {
            float4 w4 = *(float4*)&sW[k][tx * 4];
            float4 xa = *(float4*)&sX2[k][ty * 8];
            float4 xb = *(float4*)&sX2[k][ty * 8 + 4];
            float xr[8] = {xa.x, xa.y, xa.z, xa.w, xb.x, xb.y, xb.z, xb.w};
#pragma unroll
            for (int r = 0; r < 8; r++) {
                acc[r][0] += xr[r] * w4.x;
                acc[r][1] += xr[r] * w4.y;
                acc[r][2] += xr[r] * w4.z;
                acc[r][3] += xr[r] * w4.w;
            }
        }
        __syncthreads();
    }

    int h = tx >> 2;
    float4 asv = *(const float4*)&a_s[h * 16 + (tx & 3) * 4];
    float4 adv = *(const float4*)&a_d[h * 16 + (tx & 3) * 4];
    __half2* h2out = (__half2*)g_h16v;
#pragma unroll
    for (int r = 0; r < 8; r++) {
        int gr = row0 + ty * 8 + r;
        float ps = acc[r][0] * asv.x + acc[r][1] * asv.y + acc[r][2] * asv.z + acc[r][3] * asv.w;
        float pd = acc[r][0] * adv.x + acc[r][1] * adv.y + acc[r][2] * adv.z + acc[r][3] * adv.w;
        ps += __shfl_xor_sync(0xffffffffu, ps, 1);
        ps += __shfl_xor_sync(0xffffffffu, ps, 2);
        pd += __shfl_xor_sync(0xffffffffu, pd, 1);
        pd += __shfl_xor_sync(0xffffffffu, pd, 2);
        if (gr < NN) {
            h2out[(gr * 64 + tx * 4) >> 1] = __floats2half2_rn(acc[r][0], acc[r][1]);
            h2out[((gr * 64 + tx * 4) >> 1) + 1] = __floats2half2_rn(acc[r][2], acc[r][3]);
            if ((tx & 3) == 0) {
                g_als[gr * 4 + h] = ps;
                g_ald[gr * 4 + h] = pd;
            }
        }
    }
}

// ------- GEMM 64-wide (layer 2), 128-row tile, fused al + fp16 out ----
template <int IN>
__global__ void __launch_bounds__(256)
gemm64(const float* __restrict__ X, const float* __restrict__ W,
       const float* __restrict__ a_s, const float* __restrict__ a_d) {
    constexpr int KT = 32;
    constexpr int SXS = 132;
    __shared__ float sW[KT][64];
    __shared__ float sX2[KT][SXS];
    int t = threadIdx.x;
    int tx = t & 15, ty = t >> 4;
    int row0 = blockIdx.x * 128;
    float acc[8][4];
#pragma unroll
    for (int r = 0; r < 8; r++)
#pragma unroll
        for (int c = 0; c < 4; c++) acc[r][c] = 0.f;

    for (int kt = 0; kt < IN; kt += KT) {
#pragma unroll
        for (int i = t; i < KT * 16; i += 256) {
            int kk = i >> 4;
            int c4 = (i & 15) << 2;
            *(float4*)&sW[kk][c4] = *(const float4*)&W[(kt + kk) * 64 + c4];
        }
#pragma unroll
        for (int i = t; i < 128 * (KT / 4); i += 256) {
            int r = i >> 3;
            int k4 = (i & 7) << 2;
            int gr = row0 + r;
            float4 v = (gr < NN) ? *(const float4*)&X[gr * IN + kt + k4]
                                 : make_float4(0.f, 0.f, 0.f, 0.f);
            sX2[k4 + 0][r] = v.x;
            sX2[k4 + 1][r] = v.y;
            sX2[k4 + 2][r] = v.z;
            sX2[k4 + 3][r] = v.w;
        }
        __syncthreads();
#pragma unroll
        for (int k = 0; k < KT; k++) {
            float4 w4 = *(float4*)&sW[k][tx * 4];
            float4 xa = *(float4*)&sX2[k][ty * 8];
            float4 xb = *(float4*)&sX2[k][ty * 8 + 4];
            float xr[8] = {xa.x, xa.y, xa.z, xa.w, xb.x, xb.y, xb.z, xb.w};
#pragma unroll
            for (int r = 0; r < 8; r++) {
                acc[r][0] += xr[r] * w4.x;
                acc[r][1] += xr[r] * w4.y;
                acc[r][2] += xr[r] * w4.z;
                acc[r][3] += xr[r] * w4.w;
            }
        }
        __syncthreads();
    }

    int h = tx >> 2;
    float4 asv = *(const float4*)&a_s[h * 16 + (tx & 3) * 4];
    float4 adv = *(const float4*)&a_d[h * 16 + (tx & 3) * 4];
    __half2* h2out = (__half2*)g_h16v;
#pragma unroll
    for (int r = 0; r < 8; r++) {
        int gr = row0 + ty * 8 + r;
        float ps = acc[r][0] * asv.x + acc[r][1] * asv.y + acc[r][2] * asv.z + acc[r][3] * asv.w;
        float pd = acc[r][0] * adv.x + acc[r][1] * adv.y + acc[r][2] * adv.z + acc[r][3] * adv.w;
        ps += __shfl_xor_sync(0xffffffffu, ps, 1);
        ps += __shfl_xor_sync(0xffffffffu, ps, 2);
        pd += __shfl_xor_sync(0xffffffffu, pd, 1);
        pd += __shfl_xor_sync(0xffffffffu, pd, 2);
        if (gr < NN) {
            h2out[(gr * 64 + tx * 4) >> 1] = __floats2half2_rn(acc[r][0], acc[r][1]);
            h2out[((gr * 64 + tx * 4) >> 1) + 1] = __floats2half2_rn(acc[r][2], acc[r][3]);
            if ((tx & 3) == 0) {
                g_als[gr * 4 + h] = ps;
                g_ald[gr * 4 + h] = pd;
            }
        }
    }
}

// ------- GEMM layer 3 (64->16): fused al epilogue, fp16-only output -------
__global__ void gemm16(const float* __restrict__ X, const float* __restrict__ W,
                       const float* __restrict__ a_s, const float* __restrict__ a_d) {
    constexpr int IN = 64, OUT = 16;
    constexpr int RB = 64;
    __shared__ float sW[IN * OUT];
    __shared__ float sX[RB * IN];
    int t = threadIdx.x;
    int tx = t & 15, ty = t >> 4;
    int row0 = blockIdx.x * RB;

    for (int i = t; i < IN * OUT; i += 256) sW[i] = W[i];
    for (int i = t; i < RB * IN; i += 256) {
        int r = row0 + i / IN;
        sX[i] = (r < NN) ? X[r * IN + (i % IN)] : 0.f;
    }
    __syncthreads();

    float acc[4];
#pragma unroll
    for (int rr = 0; rr < 4; rr++) acc[rr] = 0.f;
    const float* xs = &sX[ty * 4 * IN];
    for (int k = 0; k < IN; k++) {
        float wv = sW[k * OUT + tx];
#pragma unroll
        for (int rr = 0; rr < 4; rr++) acc[rr] += xs[rr * IN + k] * wv;
    }
    float asx = __ldg(&a_s[tx]), adx = __ldg(&a_d[tx]);
    __half* h16 = (__half*)g_h16v;
#pragma unroll
    for (int rr = 0; rr < 4; rr++) {
        int r = row0 + ty * 4 + rr;
        float ps = acc[rr] * asx;
        float pd = acc[rr] * adx;
#pragma unroll
        for (int off = 1; off < 16; off <<= 1) {
            ps += __shfl_xor_sync(0xffffffffu, ps, off);
            pd += __shfl_xor_sync(0xffffffffu, pd, off);
        }
        if (r < NN) {
            h16[r * OUT + tx] = __float2half_rn(acc[rr]);
            if (tx == 0) {
                g_als[r] = ps;
                g_ald[r] = pd;
            }
        }
    }
}

__device__ __forceinline__ float lrelu_exp(float v) {
    v = (v > 0.f) ? v : 0.2f * v;
    return __expf(v);
}

// ============ fused gather-aggregation, 64-wide (layers 1 & 2) ============
// warp per dst node; 2 edge-halves of 16 lanes; lane owns 4 cols via LDG.64.
__global__ void __launch_bounds__(256)
agg64(const float* __restrict__ b,
      const float* __restrict__ gg, const float* __restrict__ bb,
      const float* __restrict__ mm, const float* __restrict__ vv,
      float* __restrict__ xnext) {
    __shared__ float2 sh_sex[8][4][34];
    int w = threadIdx.x >> 5;
    int lane = threadIdx.x & 31;
    int n = (blockIdx.x * blockDim.x + threadIdx.x) >> 5;
    if (n >= NN) return;
    int eg = lane >> 4;        // edge half 0/1
    int cq = lane & 15;        // col quad: cols 4*cq .. 4*cq+3
    int h = cq >> 2;           // head of those cols
    float4 ad4 = *(const float4*)&g_ald[n * 4];
    float acc0 = 0.f, acc1 = 0.f, acc2 = 0.f, acc3 = 0.f, den = 0.f;
    const uint2* pu2 = (const uint2*)g_h16v;
    int beg = g_off[n], end = g_off[n + 1];
    for (int base = beg; base < end; base += 32) {
        int idx = base + lane;
        bool valid = idx < end;
        int s = valid ? g_csr[idx] : 0;
        float4 as4 = *(const float4*)&g_als[s * 4];
        float sf = __int_as_float(s * 16);     // row base in uint2 units
        float e0 = valid ? lrelu_exp(as4.x + ad4.x) : 0.f;
        float e1 = valid ? lrelu_exp(as4.y + ad4.y) : 0.f;
        float e2 = valid ? lrelu_exp(as4.z + ad4.z) : 0.f;
        float e3 = valid ? lrelu_exp(as4.w + ad4.w) : 0.f;
        __syncwarp();
        sh_sex[w][0][lane] = make_float2(sf, e0);
        sh_sex[w][1][lane] = make_float2(sf, e1);
        sh_sex[w][2][lane] = make_float2(sf, e2);
        sh_sex[w][3][lane] = make_float2(sf, e3);
        __syncwarp();
        int nk8 = (min(32, end - base) + 7) & ~7;
        for (int j0 = 0; j0 < nk8; j0 += 8) {
#pragma unroll
            for (int u = 0; u < 4; u++) {
                int j = j0 + 2 * u + eg;
                float2 p = sh_sex[w][h][j];
                int sj16 = __float_as_int(p.x);
                float ex = p.y;
                uint2 v = __ldg(&pu2[sj16 + cq]);
                float2 f0 = __half22float2(*(__half2*)&v.x);
                float2 f1 = __half22float2(*(__half2*)&v.y);
                acc0 += ex * f0.x;
                acc1 += ex * f0.y;
                acc2 += ex * f1.x;
                acc3 += ex * f1.y;
                den += ex;
            }
        }
    }
    acc0 += __shfl_xor_sync(0xffffffffu, acc0, 16);
    acc1 += __shfl_xor_sync(0xffffffffu, acc1, 16);
    acc2 += __shfl_xor_sync(0xffffffffu, acc2, 16);
    acc3 += __shfl_xor_sync(0xffffffffu, acc3, 16);
    den += __shfl_xor_sync(0xffffffffu, den, 16);
    if (lane < 16) {
        float inv = 1.f / (den + 1e-16f);
        int c0 = 4 * cq;
        float a[4] = {acc0 * inv, acc1 * inv, acc2 * inv, acc3 * inv};
        float o[4];
#pragma unroll
        for (int i = 0; i < 4; i++) {
            int col = c0 + i;
            float y = (a[i] + __ldg(&b[col]) - __ldg(&mm[col])) *
                          rsqrtf(__ldg(&vv[col]) + 1e-5f) * __ldg(&gg[col]) +
                      __ldg(&bb[col]);
            o[i] = fmaxf(y, 0.f);
        }
        *(float4*)&xnext[n * 64 + c0] = make_float4(o[0], o[1], o[2], o[3]);
    }
}

// ============ fused gather-aggregation, 16-wide (layer 3) ============
// warp per dst node; 8 edge-groups of 4 lanes; lane owns 4 cols via uint2.
// Lean register footprint (a0..a3 + den); final reduce across groups.
__global__ void __launch_bounds__(256)
agg16() {
    __shared__ float2 sh_sex[8][33];
    int w = threadIdx.x >> 5;
    int lane = threadIdx.x & 31;
    int n = (blockIdx.x * blockDim.x + threadIdx.x) >> 5;
    if (n >= NN) return;
    int q = lane >> 2;        // edge-group 0..7
    int cg = lane & 3;        // uint2 col group: cols 4*cg .. 4*cg+3
    float ad = g_ald[n];
    float a0 = 0.f, a1 = 0.f, a2 = 0.f, a3 = 0.f, den = 0.f;
    const uint2* pu2 = (const uint2*)g_h16v;   // row = 16 halves = 4 uint2
    int beg = g_off[n], end = g_off[n + 1];
    for (int base = beg; base < end; base += 32) {
        int idx = base + lane;
        bool valid = idx < end;
        int s = valid ? g_csr[idx] : 0;
        float ex = valid ? lrelu_exp(__ldg(&g_als[s]) + ad) : 0.f;
        __syncwarp();
        sh_sex[w][lane] = make_float2(__int_as_float(s * 4), ex);
        __syncwarp();
        int nk8 = (min(32, end - base) + 7) & ~7;
        for (int j0 = 0; j0 < nk8; j0 += 8) {
            int j = j0 + q;
            float2 p = sh_sex[w][j];
            int sj4 = __float_as_int(p.x);
            float exj = p.y;
            uint2 v = __ldg(&pu2[sj4 + cg]);
            float2 f0 = __half22float2(*(__half2*)&v.x);
            float2 f1 = __half22float2(*(__half2*)&v.y);
            a0 += exj * f0.x;
            a1 += exj * f0.y;
            a2 += exj * f1.x;
            a3 += exj * f1.y;
            den += exj;
        }
    }
#pragma unroll
    for (int off = 4; off <= 16; off <<= 1) {
        a0 += __shfl_xor_sync(0xffffffffu, a0, off);
        a1 += __shfl_xor_sync(0xffffffffu, a1, off);
        a2 += __shfl_xor_sync(0xffffffffu, a2, off);
        a3 += __shfl_xor_sync(0xffffffffu, a3, off);
        den += __shfl_xor_sync(0xffffffffu, den, off);
    }
    if (lane < 4) {
        float inv = 1.f / (den + 1e-16f);
        float4 o = make_float4(a0 * inv, a1 * inv, a2 * inv, a3 * inv);
        *(float4*)&g_acc[n * 16 + 4 * cg] = o;
    }
}

// ---------------- epilogue layer 3 ----------------
__global__ void ep3(const float* __restrict__ b3, const float* __restrict__ gg,
                    const float* __restrict__ bb, const float* __restrict__ mm,
                    const float* __restrict__ vv, const float* __restrict__ fw1,
                    const float* __restrict__ fb1, const float* __restrict__ fw2,
                    const float* __restrict__ fb2, float* __restrict__ out) {
    int n = blockIdx.x * blockDim.x + threadIdx.x;
    if (n >= NN) return;
    float t[16];
#pragma unroll
    for (int c = 0; c < 16; c++) {
        float y = (g_acc[n * 16 + c] + __ldg(&b3[c]) - __ldg(&mm[c])) *
                      rsqrtf(__ldg(&vv[c]) + 1e-5f) * __ldg(&gg[c]) +
                  __ldg(&bb[c]);
        t[c] = fmaxf(y, 0.f);
    }
    float o = __ldg(&fb2[0]);
#pragma unroll
    for (int oo = 0; oo < 8; oo++) {
        float z = __ldg(&fb1[oo]);
#pragma unroll
        for (int c = 0; c < 16; c++) z += t[c] * __ldg(&fw1[c * 8 + oo]);
        z = fmaxf(z, 0.f);
        o += z * __ldg(&fw2[oo]);
    }
    out[n] = o;
}

// ---------------- launch ----------------
extern "C" void kernel_launch(void* const* d_in, const int* in_sizes, int n_in,
                              void* d_out, int out_size) {
    const float* x = (const float*)d_in[0];
    const int* ei = (const int*)d_in[1];
    const float* W1 = (const float*)d_in[2];
    const float* as1 = (const float*)d_in[3];
    const float* ad1 = (const float*)d_in[4];
    const float* b1 = (const float*)d_in[5];
    const float* g1 = (const float*)d_in[6];
    const float* bb1 = (const float*)d_in[7];
    const float* m1 = (const float*)d_in[8];
    const float* v1 = (const float*)d_in[9];
    const float* W2 = (const float*)d_in[10];
    const float* as2 = (const float*)d_in[11];
    const float* ad2 = (const float*)d_in[12];
    const float* b2 = (const float*)d_in[13];
    const float* g2 = (const float*)d_in[14];
    const float* bb2 = (const float*)d_in[15];
    const float* m2 = (const float*)d_in[16];
    const float* v2 = (const float*)d_in[17];
    const float* W3 = (const float*)d_in[18];
    const float* as3 = (const float*)d_in[19];
    const float* ad3 = (const float*)d_in[20];
    const float* b3 = (const float*)d_in[21];
    const float* g3 = (const float*)d_in[22];
    const float* bb3 = (const float*)d_in[23];
    const float* m3 = (const float*)d_in[24];
    const float* v3 = (const float*)d_in[25];
    const float* fw1 = (const float*)d_in[26];
    const float* fb1 = (const float*)d_in[27];
    const float* fw2 = (const float*)d_in[28];
    const float* fb2 = (const float*)d_in[29];
    float* out = (float*)d_out;

    float* px2 = nullptr;
    int* pdeg = nullptr;
    cudaGetSymbolAddress((void**)&px2, g_x2);
    cudaGetSymbolAddress((void**)&pdeg, g_deg);

    const int TB = 256;
    int nblk = (NN + TB - 1) / TB;
    int aggblk = (NN * 32 + TB - 1) / TB;

    // ---- CSR: hist + scan, then scatter fused with layer-1 GEMM ----
    cudaMemsetAsync(pdeg, 0, NN * sizeof(int));
    hist_kernel<<<EBLK, TB>>>(ei);
    scan_kernel<<<1, 1024>>>();

    // ---- Layer 1 GEMM || CSR scatter ----
    fused_gemm1_scatter<<<G64BLK + EBLK, TB>>>(x, W1, as1, ad1, ei);
    agg64<<<aggblk, TB>>>(b1, g1, bb1, m1, v1, px2);

    // ---- Layer 2 ----
    gemm64<64><<<G64BLK, TB>>>(px2, W2, as2, ad2);
    agg64<<<aggblk, TB>>>(b2, g2, bb2, m2, v2, px2);

    // ---- Layer 3 ----
    gemm16<<<(NN + 63) / 64, TB>>>(px2, W3, as3, ad3);
    agg16<<<aggblk, TB>>>();
    ep3<<<nblk, TB>>>(b3, g3, bb3, m3, v3, fw1, fb1, fw2, fb2, out);
}